// round 1
// baseline (speedup 1.0000x reference)
#include <cuda_runtime.h>

#define BM 128
#define BN 128
#define BK 8
#define TM 8
#define TN 8

// ---------------- scratch (device globals — no allocation allowed) ----------------
#define Bsz 4
#define Sseq 4096
#define Dd 1024

__device__ float g_K[(long long)Bsz * Sseq * Dd];   // 64 MB
__device__ float g_V[(long long)Bsz * Sseq * Dd];   // 64 MB
__device__ float g_G[(long long)Bsz * Dd * Dd];     // 16 MB
__device__ float g_s[Bsz * Dd];
__device__ float g_M[(long long)Bsz * Dd * Dd];     // 16 MB
__device__ float g_W[(long long)Bsz * Dd * Dd];     // 16 MB
__device__ float g_r[Bsz * Dd];

// ---------------- SGEMM: C = A @ B (+bias row), batched via blockIdx.z ----------------
// A: M x K row-major, B: K x N row-major, C: M x N row-major, bias: length-N row (optional)
__global__ __launch_bounds__(256) void sgemm_nn(
    const float* __restrict__ A, const float* __restrict__ B,
    const float* __restrict__ bias, float* __restrict__ C,
    int M, int N, int K,
    long long sA, long long sB, long long sBias, long long sC)
{
    int b = blockIdx.z;
    A += (long long)b * sA;
    B += (long long)b * sB;
    C += (long long)b * sC;
    if (bias) bias += (long long)b * sBias;

    __shared__ float As[BK][BM];
    __shared__ float Bs[BK][BN];

    const int tid = threadIdx.x;
    const int bm = blockIdx.y * BM;
    const int bn = blockIdx.x * BN;

    // A tile load: 128 rows x 8 cols -> 2 float4 per row
    const int arow = tid >> 1;
    const int acol = (tid & 1) * 4;
    // B tile load: 8 rows x 128 cols -> 32 float4 per row
    const int brow = tid >> 5;
    const int bcol = (tid & 31) * 4;

    const int tr = (tid >> 4) * TM;
    const int tc = (tid & 15) * TN;

    float acc[TM][TN] = {};
    float ra[TM], rb[TN];

    for (int k0 = 0; k0 < K; k0 += BK) {
        float4 a4 = *reinterpret_cast<const float4*>(&A[(long long)(bm + arow) * K + k0 + acol]);
        As[acol + 0][arow] = a4.x;
        As[acol + 1][arow] = a4.y;
        As[acol + 2][arow] = a4.z;
        As[acol + 3][arow] = a4.w;
        float4 b4 = *reinterpret_cast<const float4*>(&B[(long long)(k0 + brow) * N + bn + bcol]);
        *reinterpret_cast<float4*>(&Bs[brow][bcol]) = b4;
        __syncthreads();
        #pragma unroll
        for (int kk = 0; kk < BK; kk++) {
            #pragma unroll
            for (int i = 0; i < TM; i++) ra[i] = As[kk][tr + i];
            #pragma unroll
            for (int j = 0; j < TN; j++) rb[j] = Bs[kk][tc + j];
            #pragma unroll
            for (int i = 0; i < TM; i++)
                #pragma unroll
                for (int j = 0; j < TN; j++)
                    acc[i][j] += ra[i] * rb[j];
        }
        __syncthreads();
    }

    #pragma unroll
    for (int i = 0; i < TM; i++) {
        #pragma unroll
        for (int j = 0; j < TN; j += 4) {
            float4 v;
            v.x = acc[i][j + 0];
            v.y = acc[i][j + 1];
            v.z = acc[i][j + 2];
            v.w = acc[i][j + 3];
            if (bias) {
                v.x += bias[bn + tc + j + 0];
                v.y += bias[bn + tc + j + 1];
                v.z += bias[bn + tc + j + 2];
                v.w += bias[bn + tc + j + 3];
            }
            *reinterpret_cast<float4*>(&C[(long long)(bm + tr + i) * N + bn + tc + j]) = v;
        }
    }
}

// ---------------- SGEMM: C = A^T @ B, batched ----------------
// A: Kdim x M row-major (lda = M), B: Kdim x N row-major, C: M x N row-major
__global__ __launch_bounds__(256) void sgemm_tn(
    const float* __restrict__ A, const float* __restrict__ B,
    float* __restrict__ C,
    int M, int N, int K,
    long long sA, long long sB, long long sC)
{
    int b = blockIdx.z;
    A += (long long)b * sA;
    B += (long long)b * sB;
    C += (long long)b * sC;

    __shared__ float As[BK][BM];
    __shared__ float Bs[BK][BN];

    const int tid = threadIdx.x;
    const int bm = blockIdx.y * BM;
    const int bn = blockIdx.x * BN;

    // A^T tile load: 8 k-rows x 128 m-cols, coalesced (A is row-major with M cols)
    const int arow = tid >> 5;          // k within tile
    const int acol = (tid & 31) * 4;    // m within tile
    const int brow = tid >> 5;
    const int bcol = (tid & 31) * 4;

    const int tr = (tid >> 4) * TM;
    const int tc = (tid & 15) * TN;

    float acc[TM][TN] = {};
    float ra[TM], rb[TN];

    for (int k0 = 0; k0 < K; k0 += BK) {
        float4 a4 = *reinterpret_cast<const float4*>(&A[(long long)(k0 + arow) * M + bm + acol]);
        *reinterpret_cast<float4*>(&As[arow][acol]) = a4;
        float4 b4 = *reinterpret_cast<const float4*>(&B[(long long)(k0 + brow) * N + bn + bcol]);
        *reinterpret_cast<float4*>(&Bs[brow][bcol]) = b4;
        __syncthreads();
        #pragma unroll
        for (int kk = 0; kk < BK; kk++) {
            #pragma unroll
            for (int i = 0; i < TM; i++) ra[i] = As[kk][tr + i];
            #pragma unroll
            for (int j = 0; j < TN; j++) rb[j] = Bs[kk][tc + j];
            #pragma unroll
            for (int i = 0; i < TM; i++)
                #pragma unroll
                for (int j = 0; j < TN; j++)
                    acc[i][j] += ra[i] * rb[j];
        }
        __syncthreads();
    }

    #pragma unroll
    for (int i = 0; i < TM; i++) {
        #pragma unroll
        for (int j = 0; j < TN; j += 4) {
            float4 v;
            v.x = acc[i][j + 0];
            v.y = acc[i][j + 1];
            v.z = acc[i][j + 2];
            v.w = acc[i][j + 3];
            *reinterpret_cast<float4*>(&C[(long long)(bm + tr + i) * N + bn + tc + j]) = v;
        }
    }
}

// ---------------- s_b[n] = sum_j G_b[j, (n-j) mod D] ----------------
__global__ void reduce_s(const float* __restrict__ G, float* __restrict__ s)
{
    int b = blockIdx.y;
    int n = blockIdx.x * blockDim.x + threadIdx.x;
    const float* Gb = G + (long long)b * Dd * Dd;
    float acc = 0.f;
    #pragma unroll 4
    for (int j = 0; j < Dd; j++)
        acc += Gb[(long long)j * Dd + ((n - j) & (Dd - 1))];
    s[b * Dd + n] = acc;
}

// ---------------- M_b[m,n] = s_b[(m+n) mod D] ----------------
__global__ void build_M(const float* __restrict__ s, float* __restrict__ Mmat)
{
    int b = blockIdx.z;
    int m = blockIdx.y;
    int n = blockIdx.x * blockDim.x + threadIdx.x;
    Mmat[(long long)b * Dd * Dd + (long long)m * Dd + n] = s[b * Dd + ((m + n) & (Dd - 1))];
}

// ---------------- r_b[n] = sum_m bq[m] * s_b[(m+n) mod D] ----------------
__global__ void compute_r(const float* __restrict__ s, const float* __restrict__ bq,
                          float* __restrict__ r)
{
    int b = blockIdx.y;
    int n = blockIdx.x * blockDim.x + threadIdx.x;
    float acc = 0.f;
    for (int m = 0; m < Dd; m++)
        acc += bq[m] * s[b * Dd + ((m + n) & (Dd - 1))];
    r[b * Dd + n] = acc;
}

extern "C" void kernel_launch(void* const* d_in, const int* in_sizes, int n_in,
                              void* d_out, int out_size)
{
    const float* x  = (const float*)d_in[0];
    const float* Wq = (const float*)d_in[1];
    const float* bq = (const float*)d_in[2];
    const float* Wk = (const float*)d_in[3];
    const float* bk = (const float*)d_in[4];
    const float* Wv = (const float*)d_in[5];
    const float* bv = (const float*)d_in[6];
    float* out = (float*)d_out;

    float *pK, *pV, *pG, *ps, *pM, *pW, *pr;
    cudaGetSymbolAddress((void**)&pK, g_K);
    cudaGetSymbolAddress((void**)&pV, g_V);
    cudaGetSymbolAddress((void**)&pG, g_G);
    cudaGetSymbolAddress((void**)&ps, g_s);
    cudaGetSymbolAddress((void**)&pM, g_M);
    cudaGetSymbolAddress((void**)&pW, g_W);
    cudaGetSymbolAddress((void**)&pr, g_r);

    const int BS = Bsz * Sseq;            // 16384 rows
    const long long xb   = (long long)Sseq * Dd;   // per-batch x / K / V / out stride
    const long long dd   = (long long)Dd * Dd;

    dim3 blk(256);

    // 1) K = x @ Wk + bk ; V = x @ Wv + bv   (treat x as (B*S) x D)
    sgemm_nn<<<dim3(Dd / BN, BS / BM, 1), blk>>>(x, Wk, bk, pK, BS, Dd, Dd, 0, 0, 0, 0);
    sgemm_nn<<<dim3(Dd / BN, BS / BM, 1), blk>>>(x, Wv, bv, pV, BS, Dd, Dd, 0, 0, 0, 0);

    // 2) G_b = K_b^T @ V_b  (1024x1024x4096, batched over 4)
    sgemm_tn<<<dim3(Dd / BN, Dd / BM, Bsz), blk>>>(pK, pV, pG, Dd, Dd, Sseq, xb, xb, dd);

    // 3) s_b[n] = circular anti-diagonal sum of G_b
    reduce_s<<<dim3(Dd / 256, Bsz), 256>>>(pG, ps);

    // 4) M_b[m,n] = s_b[(m+n)%D];  r_b = bq @ M_b
    build_M<<<dim3(Dd / 256, Dd, Bsz), 256>>>(ps, pM);
    compute_r<<<dim3(Dd / 256, Bsz), 256>>>(ps, bq, pr);

    // 5) W_b = Wq @ M_b  (1024^3, batched)
    sgemm_nn<<<dim3(Dd / BN, Dd / BM, Bsz), blk>>>(Wq, pM, nullptr, pW, Dd, Dd, Dd,
                                                   0, dd, 0, dd);

    // 6) out_b = x_b @ W_b + r_b  (4096x1024x1024, batched)
    sgemm_nn<<<dim3(Dd / BN, Sseq / BM, Bsz), blk>>>(x, pW, pr, out, Sseq, Dd, Dd,
                                                     xb, dd, Dd, xb);
}

// round 3
// speedup vs baseline: 2.4495x; 2.4495x over previous
#include <cuda_runtime.h>
#include <cuda_bf16.h>
#include <stdint.h>

#define Bsz 4
#define Sq  4096
#define Dd  1024
#define BS  (Bsz * Sq)   // 16384

// ---------------- scratch (device globals — allocation is forbidden) ----------------
__device__ __align__(256) __nv_bfloat16 g_xh[(long long)BS * Dd];
__device__ __align__(256) __nv_bfloat16 g_xl[(long long)BS * Dd];
__device__ __align__(256) __nv_bfloat16 g_WkTh[Dd * Dd];
__device__ __align__(256) __nv_bfloat16 g_WkTl[Dd * Dd];
__device__ __align__(256) __nv_bfloat16 g_WvTh[Dd * Dd];
__device__ __align__(256) __nv_bfloat16 g_WvTl[Dd * Dd];
__device__ __align__(256) __nv_bfloat16 g_Wqh[Dd * Dd];
__device__ __align__(256) __nv_bfloat16 g_Wql[Dd * Dd];
__device__ __align__(256) float         g_Kf[(long long)BS * Dd];
__device__ __align__(256) float         g_Vf[(long long)BS * Dd];
__device__ __align__(256) __nv_bfloat16 g_KTh[(long long)BS * Dd];
__device__ __align__(256) __nv_bfloat16 g_KTl[(long long)BS * Dd];
__device__ __align__(256) __nv_bfloat16 g_VTh[(long long)BS * Dd];
__device__ __align__(256) __nv_bfloat16 g_VTl[(long long)BS * Dd];
__device__ __align__(256) float         g_G[(long long)Bsz * Dd * Dd];
__device__ __align__(256) float         g_s[Bsz * Dd];
__device__ __align__(256) float         g_r[Bsz * Dd];
__device__ __align__(256) __nv_bfloat16 g_Mh[(long long)Bsz * Dd * Dd];
__device__ __align__(256) __nv_bfloat16 g_Ml[(long long)Bsz * Dd * Dd];
__device__ __align__(256) float         g_W2T[(long long)Bsz * Dd * Dd];
__device__ __align__(256) __nv_bfloat16 g_W2Th[(long long)Bsz * Dd * Dd];
__device__ __align__(256) __nv_bfloat16 g_W2Tl[(long long)Bsz * Dd * Dd];

// ---------------- PTX helpers (sm_80-era only: cp.async / ldmatrix / mma.sync) ----------------
__device__ __forceinline__ uint32_t smem_u32(const void* p) {
    uint32_t a;
    asm("{ .reg .u64 t; cvta.to.shared.u64 t, %1; cvt.u32.u64 %0, t; }" : "=r"(a) : "l"(p));
    return a;
}
__device__ __forceinline__ void cp16(uint32_t dst, const void* src) {
    asm volatile("cp.async.cg.shared.global [%0], [%1], 16;" :: "r"(dst), "l"(src));
}
__device__ __forceinline__ void cp_commit() { asm volatile("cp.async.commit_group;" ::: "memory"); }
__device__ __forceinline__ void cp_wait1()  { asm volatile("cp.async.wait_group 1;" ::: "memory"); }
__device__ __forceinline__ void cp_wait0()  { asm volatile("cp.async.wait_group 0;" ::: "memory"); }

__device__ __forceinline__ void ldsm_x4(uint32_t& r0, uint32_t& r1, uint32_t& r2, uint32_t& r3,
                                        uint32_t addr) {
    asm volatile("ldmatrix.sync.aligned.m8n8.x4.shared.b16 {%0,%1,%2,%3}, [%4];"
                 : "=r"(r0), "=r"(r1), "=r"(r2), "=r"(r3) : "r"(addr));
}
__device__ __forceinline__ void mma_bf16(float& c0, float& c1, float& c2, float& c3,
                                         uint32_t a0, uint32_t a1, uint32_t a2, uint32_t a3,
                                         uint32_t b0, uint32_t b1) {
    asm volatile(
        "mma.sync.aligned.m16n8k16.row.col.f32.bf16.bf16.f32 "
        "{%0,%1,%2,%3}, {%4,%5,%6,%7}, {%8,%9}, {%0,%1,%2,%3};"
        : "+f"(c0), "+f"(c1), "+f"(c2), "+f"(c3)
        : "r"(a0), "r"(a1), "r"(a2), "r"(a3), "r"(b0), "r"(b1));
}

// ---------------- split-bf16 HMMA GEMM: C[M,N] = (Ah+Al)(Bh+Bl)^T (+bias[n]) ----------------
// A: [M,K] row-major bf16 hi/lo. B: [N,K] row-major bf16 hi/lo (i.e. col-major B for mma).
// CTA tile 128(M) x 256(N) x 32(K), 8 warps of 64x64, double-buffered cp.async.
// SMEM per stage: Ah,Al 128x32 (rows padded to 80B) + Bh,Bl 256x32.
#define ROWB   80
#define A_PL   (128 * ROWB)          // 10240
#define B_PL   (256 * ROWB)          // 20480
#define STG    (2 * A_PL + 2 * B_PL) // 61440
#define GEMM_DSMEM (2 * STG)         // 122880

__global__ __launch_bounds__(256, 1) void gemm_hmma(
    const __nv_bfloat16* __restrict__ Ah, const __nv_bfloat16* __restrict__ Al,
    const __nv_bfloat16* __restrict__ Bh, const __nv_bfloat16* __restrict__ Bl,
    const float* __restrict__ bias, float* __restrict__ C,
    int N, int Ktot,
    long long sA, long long sB, long long sBias, long long sC)
{
    extern __shared__ __align__(128) char smem[];
    const int tid = threadIdx.x;
    const int wid = tid >> 5, lid = tid & 31;
    const int bz = blockIdx.z;
    const long long bm = (long long)blockIdx.y * 128;
    const long long bn = (long long)blockIdx.x * 256;

    const __nv_bfloat16* gA[2] = { Ah + bz * sA + bm * Ktot, Al + bz * sA + bm * Ktot };
    const __nv_bfloat16* gB[2] = { Bh + bz * sB + bn * Ktot, Bl + bz * sB + bn * Ktot };
    C += bz * sC;
    const float* biasp = bias ? bias + bz * sBias : nullptr;

    const uint32_t sb = smem_u32(smem);

    // warp tile: 64x64.  warp grid: 2 (M) x 4 (N)
    const int wm = (wid & 1) * 64;
    const int wn = (wid >> 1) * 64;

    float acc[128];
    #pragma unroll
    for (int i = 0; i < 128; i++) acc[i] = 0.f;

    auto load_chunk = [&](int p, int k0) {
        uint32_t buf = sb + p * STG;
        #pragma unroll
        for (int pl = 0; pl < 2; pl++) {
            const __nv_bfloat16* g = gA[pl] + k0;
            #pragma unroll
            for (int it = 0; it < 2; it++) {              // 512 chunks / 256 thr
                int id = tid + it * 256;
                int r = id >> 2, ch = id & 3;
                cp16(buf + pl * A_PL + r * ROWB + ch * 16,
                     g + (long long)r * Ktot + ch * 8);
            }
        }
        #pragma unroll
        for (int pl = 0; pl < 2; pl++) {
            const __nv_bfloat16* g = gB[pl] + k0;
            #pragma unroll
            for (int it = 0; it < 4; it++) {              // 1024 chunks / 256 thr
                int id = tid + it * 256;
                int r = id >> 2, ch = id & 3;
                cp16(buf + 2 * A_PL + pl * B_PL + r * ROWB + ch * 16,
                     g + (long long)r * Ktot + ch * 8);
            }
        }
        cp_commit();
    };

    const int nc = Ktot >> 5;
    load_chunk(0, 0);

    // per-lane ldmatrix address components
    const int a_row = wm + (lid & 15);            // + mb*16
    const int a_kb  = (lid >> 4) * 16;            // 16B k-half select
    const int b_row = wn + (lid & 7) + ((lid >> 4) & 1) * 8;  // + nbp*16
    const int b_kb  = ((lid >> 3) & 1) * 16;

    for (int i = 0; i < nc; i++) {
        if (i + 1 < nc) { load_chunk((i + 1) & 1, (i + 1) << 5); cp_wait1(); }
        else            { cp_wait0(); }
        __syncthreads();

        const uint32_t buf = sb + (i & 1) * STG;
        #pragma unroll
        for (int kk = 0; kk < 2; kk++) {
            const uint32_t koff = kk * 32;
            // A fragments: 4 m-blocks x (hi,lo)
            uint32_t Afr[2][4][4];
            #pragma unroll
            for (int pl = 0; pl < 2; pl++) {
                const uint32_t abase = buf + pl * A_PL + koff + a_kb;
                #pragma unroll
                for (int mb = 0; mb < 4; mb++)
                    ldsm_x4(Afr[pl][mb][0], Afr[pl][mb][1], Afr[pl][mb][2], Afr[pl][mb][3],
                            abase + (a_row + mb * 16) * ROWB);
            }
            // B: 4 pairs of n8-blocks
            #pragma unroll
            for (int nbp = 0; nbp < 4; nbp++) {
                uint32_t Bh0, Bh1, Bh2, Bh3, Bl0, Bl1, Bl2, Bl3;
                const uint32_t bb = buf + 2 * A_PL + (b_row + nbp * 16) * ROWB + koff + b_kb;
                ldsm_x4(Bh0, Bh1, Bh2, Bh3, bb);
                ldsm_x4(Bl0, Bl1, Bl2, Bl3, bb + B_PL);
                #pragma unroll
                for (int half = 0; half < 2; half++) {
                    const int nb = nbp * 2 + half;
                    const uint32_t bh0 = half ? Bh2 : Bh0, bh1 = half ? Bh3 : Bh1;
                    const uint32_t bl0 = half ? Bl2 : Bl0, bl1 = half ? Bl3 : Bl1;
                    #pragma unroll
                    for (int mb = 0; mb < 4; mb++) {
                        float* c = &acc[(mb * 8 + nb) * 4];
                        mma_bf16(c[0], c[1], c[2], c[3],
                                 Afr[0][mb][0], Afr[0][mb][1], Afr[0][mb][2], Afr[0][mb][3],
                                 bh0, bh1);
                        mma_bf16(c[0], c[1], c[2], c[3],
                                 Afr[0][mb][0], Afr[0][mb][1], Afr[0][mb][2], Afr[0][mb][3],
                                 bl0, bl1);
                        mma_bf16(c[0], c[1], c[2], c[3],
                                 Afr[1][mb][0], Afr[1][mb][1], Afr[1][mb][2], Afr[1][mb][3],
                                 bh0, bh1);
                    }
                }
            }
        }
        __syncthreads();
    }

    // epilogue: lane l of warp -> rows l/4, l/4+8; cols 2*(l%4), +1 within each m16n8 block
    const int er = lid >> 2;
    const int ec = (lid & 3) * 2;
    #pragma unroll
    for (int mb = 0; mb < 4; mb++) {
        #pragma unroll
        for (int nb = 0; nb < 8; nb++) {
            const float* c = &acc[(mb * 8 + nb) * 4];
            long long col = bn + wn + nb * 8 + ec;
            float bx = 0.f, by = 0.f;
            if (biasp) { bx = biasp[col]; by = biasp[col + 1]; }
            long long r0 = bm + wm + mb * 16 + er;
            float2 v0 = { c[0] + bx, c[1] + by };
            float2 v1 = { c[2] + bx, c[3] + by };
            *reinterpret_cast<float2*>(C + r0 * N + col) = v0;
            *reinterpret_cast<float2*>(C + (r0 + 8) * N + col) = v1;
        }
    }
}

// ---------------- prep kernels ----------------
__global__ void split_conv(const float* __restrict__ s, __nv_bfloat16* __restrict__ h,
                           __nv_bfloat16* __restrict__ l, long long n)
{
    long long i = (long long)blockIdx.x * blockDim.x + threadIdx.x;
    if (i < n) {
        float v = s[i];
        __nv_bfloat16 hi = __float2bfloat16(v);
        h[i] = hi;
        l[i] = __float2bfloat16(v - __bfloat162float(hi));
    }
}

// out[c][r] = src[r][c]; src: [R, C] fp32, out: [C, R] bf16 hi/lo; batched via z
__global__ void transpose_split(const float* __restrict__ src,
                                __nv_bfloat16* __restrict__ dh, __nv_bfloat16* __restrict__ dl,
                                int R, int C, long long sIn, long long sOut)
{
    __shared__ float t[32][33];
    int b = blockIdx.z;
    src += (long long)b * sIn; dh += (long long)b * sOut; dl += (long long)b * sOut;
    int c0 = blockIdx.x * 32, r0 = blockIdx.y * 32;
    int tx = threadIdx.x, ty = threadIdx.y;
    #pragma unroll
    for (int k = 0; k < 32; k += 8)
        t[ty + k][tx] = src[(long long)(r0 + ty + k) * C + c0 + tx];
    __syncthreads();
    #pragma unroll
    for (int k = 0; k < 32; k += 8) {
        float v = t[tx][ty + k];
        __nv_bfloat16 hi = __float2bfloat16(v);
        long long o = (long long)(c0 + ty + k) * R + r0 + tx;
        dh[o] = hi;
        dl[o] = __float2bfloat16(v - __bfloat162float(hi));
    }
}

__global__ void zero_s(float* p) { p[blockIdx.x * 256 + threadIdx.x] = 0.f; }

// s_b[n] += sum_{j in band} G_b[j, (n-j) mod D]   grid (4, 8, Bsz)
__global__ void reduce_s2(const float* __restrict__ G, float* __restrict__ s)
{
    int b = blockIdx.z;
    int n = blockIdx.x * 256 + threadIdx.x;
    int j0 = blockIdx.y * 128;
    const float* Gb = G + ((long long)b << 20);
    float acc = 0.f;
    #pragma unroll 4
    for (int j = j0; j < j0 + 128; j++)
        acc += Gb[((long long)j << 10) + ((n - j) & (Dd - 1))];
    atomicAdd(&s[b * Dd + n], acc);
}

// M_b[k][n] = s_b[(k+n) mod D]  (hi/lo)   grid (4, 1024, Bsz)
__global__ void build_M_split(const float* __restrict__ s,
                              __nv_bfloat16* __restrict__ h, __nv_bfloat16* __restrict__ l)
{
    int b = blockIdx.z, k = blockIdx.y;
    int n = blockIdx.x * 256 + threadIdx.x;
    float v = s[b * Dd + ((k + n) & (Dd - 1))];
    __nv_bfloat16 hi = __float2bfloat16(v);
    long long o = ((long long)b << 20) + ((long long)k << 10) + n;
    h[o] = hi;
    l[o] = __float2bfloat16(v - __bfloat162float(hi));
}

// r_b[n] = sum_m bq[m] * s_b[(m+n) mod D]   grid (4, Bsz)
__global__ void compute_r(const float* __restrict__ s, const float* __restrict__ bq,
                          float* __restrict__ r)
{
    int b = blockIdx.y;
    int n = blockIdx.x * 256 + threadIdx.x;
    float acc = 0.f;
    for (int m = 0; m < Dd; m++)
        acc += bq[m] * s[b * Dd + ((m + n) & (Dd - 1))];
    r[b * Dd + n] = acc;
}

// ---------------- launcher ----------------
extern "C" void kernel_launch(void* const* d_in, const int* in_sizes, int n_in,
                              void* d_out, int out_size)
{
    const float* x  = (const float*)d_in[0];
    const float* Wq = (const float*)d_in[1];
    const float* bq = (const float*)d_in[2];
    const float* Wk = (const float*)d_in[3];
    const float* bk = (const float*)d_in[4];
    const float* Wv = (const float*)d_in[5];
    const float* bv = (const float*)d_in[6];
    float* out = (float*)d_out;

    __nv_bfloat16 *xh, *xl, *WkTh, *WkTl, *WvTh, *WvTl, *Wqh, *Wql;
    __nv_bfloat16 *KTh, *KTl, *VTh, *VTl, *Mh, *Ml, *W2Th, *W2Tl;
    float *Kf, *Vf, *G, *s, *r, *W2T;
    cudaGetSymbolAddress((void**)&xh, g_xh);     cudaGetSymbolAddress((void**)&xl, g_xl);
    cudaGetSymbolAddress((void**)&WkTh, g_WkTh); cudaGetSymbolAddress((void**)&WkTl, g_WkTl);
    cudaGetSymbolAddress((void**)&WvTh, g_WvTh); cudaGetSymbolAddress((void**)&WvTl, g_WvTl);
    cudaGetSymbolAddress((void**)&Wqh, g_Wqh);   cudaGetSymbolAddress((void**)&Wql, g_Wql);
    cudaGetSymbolAddress((void**)&Kf, g_Kf);     cudaGetSymbolAddress((void**)&Vf, g_Vf);
    cudaGetSymbolAddress((void**)&KTh, g_KTh);   cudaGetSymbolAddress((void**)&KTl, g_KTl);
    cudaGetSymbolAddress((void**)&VTh, g_VTh);   cudaGetSymbolAddress((void**)&VTl, g_VTl);
    cudaGetSymbolAddress((void**)&G, g_G);       cudaGetSymbolAddress((void**)&s, g_s);
    cudaGetSymbolAddress((void**)&r, g_r);
    cudaGetSymbolAddress((void**)&Mh, g_Mh);     cudaGetSymbolAddress((void**)&Ml, g_Ml);
    cudaGetSymbolAddress((void**)&W2T, g_W2T);
    cudaGetSymbolAddress((void**)&W2Th, g_W2Th); cudaGetSymbolAddress((void**)&W2Tl, g_W2Tl);

    cudaFuncSetAttribute(gemm_hmma, cudaFuncAttributeMaxDynamicSharedMemorySize, GEMM_DSMEM);

    const long long nBS = (long long)BS * Dd;       // 16M
    const long long dd  = (long long)Dd * Dd;       // 1M
    const long long sd  = (long long)Sq * Dd;       // 4M

    // 0) convert inputs to bf16 hi/lo (Wk, Wv transposed so GEMM B-operand is [N,K])
    split_conv<<<(unsigned)((nBS + 255) / 256), 256>>>(x, xh, xl, nBS);
    transpose_split<<<dim3(Dd / 32, Dd / 32, 1), dim3(32, 8)>>>(Wk, WkTh, WkTl, Dd, Dd, 0, 0);
    transpose_split<<<dim3(Dd / 32, Dd / 32, 1), dim3(32, 8)>>>(Wv, WvTh, WvTl, Dd, Dd, 0, 0);
    split_conv<<<(unsigned)((dd + 255) / 256), 256>>>(Wq, Wqh, Wql, dd);

    // 1) K = x@Wk + bk ; V = x@Wv + bv   (M=16384, N=1024, K=1024)
    gemm_hmma<<<dim3(Dd / 256, BS / 128, 1), 256, GEMM_DSMEM>>>(
        xh, xl, WkTh, WkTl, bk, Kf, Dd, Dd, 0, 0, 0, 0);
    gemm_hmma<<<dim3(Dd / 256, BS / 128, 1), 256, GEMM_DSMEM>>>(
        xh, xl, WvTh, WvTl, bv, Vf, Dd, Dd, 0, 0, 0, 0);

    // 2) transpose+split K,V per batch: [S,D] -> [D,S] bf16 hi/lo
    transpose_split<<<dim3(Dd / 32, Sq / 32, Bsz), dim3(32, 8)>>>(Kf, KTh, KTl, Sq, Dd, sd, sd);
    transpose_split<<<dim3(Dd / 32, Sq / 32, Bsz), dim3(32, 8)>>>(Vf, VTh, VTl, Sq, Dd, sd, sd);

    // 3) G_b = K_b^T @ V_b  (M=N=1024, K=4096, batched)
    gemm_hmma<<<dim3(Dd / 256, Dd / 128, Bsz), 256, GEMM_DSMEM>>>(
        KTh, KTl, VTh, VTl, nullptr, G, Dd, Sq, sd, sd, 0, dd);

    // 4) s_b[n] = circular anti-diagonal sum of G_b
    zero_s<<<Bsz * Dd / 256, 256>>>(s);
    reduce_s2<<<dim3(Dd / 256, 8, Bsz), 256>>>(G, s);

    // 5) M_b (bf16 hi/lo), r_b = bq @ M_b
    build_M_split<<<dim3(Dd / 256, Dd, Bsz), 256>>>(s, Mh, Ml);
    compute_r<<<dim3(Dd / 256, Bsz), 256>>>(s, bq, r);

    // 6) W2T_b = M_b @ Wq^T  (M=N=1024, K=1024, batched; Wq natural layout = [N,K])
    gemm_hmma<<<dim3(Dd / 256, Dd / 128, Bsz), 256, GEMM_DSMEM>>>(
        Mh, Ml, Wqh, Wql, nullptr, W2T, Dd, Dd, dd, 0, 0, dd);
    split_conv<<<(unsigned)((Bsz * dd + 255) / 256), 256>>>(W2T, W2Th, W2Tl, Bsz * dd);

    // 7) out_b = x_b @ W2_b + r_b  (M=4096, N=1024, K=1024, batched; B = W2T natural)
    gemm_hmma<<<dim3(Dd / 256, Sq / 128, Bsz), 256, GEMM_DSMEM>>>(
        xh, xl, W2Th, W2Tl, r, out, Dd, Dd, sd, dd, Dd, sd);
}

// round 4
// speedup vs baseline: 2.7324x; 1.1155x over previous
#include <cuda_runtime.h>
#include <cuda_bf16.h>
#include <stdint.h>

#define Bsz 4
#define Sq  4096
#define Dd  1024
#define BS  (Bsz * Sq)   // 16384

// ---------------- scratch (device globals — allocation is forbidden) ----------------
__device__ __align__(256) __nv_bfloat16 g_xh[(long long)BS * Dd];
__device__ __align__(256) __nv_bfloat16 g_xl[(long long)BS * Dd];
__device__ __align__(256) __nv_bfloat16 g_WkTh[Dd * Dd];
__device__ __align__(256) __nv_bfloat16 g_WkTl[Dd * Dd];
__device__ __align__(256) __nv_bfloat16 g_WvTh[Dd * Dd];
__device__ __align__(256) __nv_bfloat16 g_WvTl[Dd * Dd];
__device__ __align__(256) __nv_bfloat16 g_Wqh[Dd * Dd];
__device__ __align__(256) __nv_bfloat16 g_Wql[Dd * Dd];
__device__ __align__(256) __nv_bfloat16 g_Kh[(long long)BS * Dd];
__device__ __align__(256) __nv_bfloat16 g_Kl[(long long)BS * Dd];
__device__ __align__(256) __nv_bfloat16 g_Vh[(long long)BS * Dd];
__device__ __align__(256) __nv_bfloat16 g_Vl[(long long)BS * Dd];
__device__ __align__(256) __nv_bfloat16 g_KTh[(long long)BS * Dd];
__device__ __align__(256) __nv_bfloat16 g_KTl[(long long)BS * Dd];
__device__ __align__(256) __nv_bfloat16 g_VTh[(long long)BS * Dd];
__device__ __align__(256) __nv_bfloat16 g_VTl[(long long)BS * Dd];
__device__ __align__(256) float         g_G[(long long)Bsz * Dd * Dd];
__device__ __align__(256) float         g_s[Bsz * Dd];
__device__ __align__(256) float         g_r[Bsz * Dd];
__device__ __align__(256) __nv_bfloat16 g_Mh[(long long)Bsz * Dd * Dd];
__device__ __align__(256) __nv_bfloat16 g_Ml[(long long)Bsz * Dd * Dd];
__device__ __align__(256) __nv_bfloat16 g_W2Th[(long long)Bsz * Dd * Dd];
__device__ __align__(256) __nv_bfloat16 g_W2Tl[(long long)Bsz * Dd * Dd];

// ---------------- PTX helpers ----------------
__device__ __forceinline__ uint32_t smem_u32(const void* p) {
    uint32_t a;
    asm("{ .reg .u64 t; cvta.to.shared.u64 t, %1; cvt.u32.u64 %0, t; }" : "=r"(a) : "l"(p));
    return a;
}
__device__ __forceinline__ void cp16(uint32_t dst, const void* src) {
    asm volatile("cp.async.cg.shared.global [%0], [%1], 16;" :: "r"(dst), "l"(src));
}
__device__ __forceinline__ void cp_commit() { asm volatile("cp.async.commit_group;" ::: "memory"); }
__device__ __forceinline__ void cp_wait1()  { asm volatile("cp.async.wait_group 1;" ::: "memory"); }
__device__ __forceinline__ void cp_wait0()  { asm volatile("cp.async.wait_group 0;" ::: "memory"); }

__device__ __forceinline__ void ldsm_x4(uint32_t& r0, uint32_t& r1, uint32_t& r2, uint32_t& r3,
                                        uint32_t addr) {
    asm volatile("ldmatrix.sync.aligned.m8n8.x4.shared.b16 {%0,%1,%2,%3}, [%4];"
                 : "=r"(r0), "=r"(r1), "=r"(r2), "=r"(r3) : "r"(addr));
}
__device__ __forceinline__ void mma_bf16(float& c0, float& c1, float& c2, float& c3,
                                         uint32_t a0, uint32_t a1, uint32_t a2, uint32_t a3,
                                         uint32_t b0, uint32_t b1) {
    asm volatile(
        "mma.sync.aligned.m16n8k16.row.col.f32.bf16.bf16.f32 "
        "{%0,%1,%2,%3}, {%4,%5,%6,%7}, {%8,%9}, {%0,%1,%2,%3};"
        : "+f"(c0), "+f"(c1), "+f"(c2), "+f"(c3)
        : "r"(a0), "r"(a1), "r"(a2), "r"(a3), "r"(b0), "r"(b1));
}

// ---------------- split-bf16 HMMA GEMM: C[M,N] = (Ah+Al)(Bh+Bl)^T (+bias[n]) ----------------
// A: [M,K] row-major bf16 hi/lo.  B: [N,K] row-major bf16 hi/lo.
// CTA tile 128x128x32, 8 warps of 32x64, double-buffered cp.async, 2 CTAs/SM.
// Output: fp32 (Cf) OR bf16 hi/lo split (Ch, Cl).
#define ROWB   80
#define A_PL   (128 * ROWB)          // 10240
#define B_PL   (128 * ROWB)          // 10240
#define STG    (2 * A_PL + 2 * B_PL) // 40960
#define GEMM_DSMEM (2 * STG)         // 81920

__global__ __launch_bounds__(256, 2) void gemm_hmma(
    const __nv_bfloat16* __restrict__ Ah, const __nv_bfloat16* __restrict__ Al,
    const __nv_bfloat16* __restrict__ Bh, const __nv_bfloat16* __restrict__ Bl,
    const float* __restrict__ bias, float* __restrict__ Cf,
    __nv_bfloat16* __restrict__ Ch, __nv_bfloat16* __restrict__ Cl,
    int N, int Ktot,
    long long sA, long long sB, long long sBias, long long sC)
{
    extern __shared__ __align__(128) char smem[];
    const int tid = threadIdx.x;
    const int wid = tid >> 5, lid = tid & 31;
    const int bz = blockIdx.z;
    const long long bm = (long long)blockIdx.y * 128;
    const long long bn = (long long)blockIdx.x * 128;

    const __nv_bfloat16* gA[2] = { Ah + bz * sA + bm * Ktot, Al + bz * sA + bm * Ktot };
    const __nv_bfloat16* gB[2] = { Bh + bz * sB + bn * Ktot, Bl + bz * sB + bn * Ktot };
    const float* biasp = bias ? bias + bz * sBias : nullptr;

    const uint32_t sb = smem_u32(smem);

    // warp tile 32(M) x 64(N): 4 warps along M, 2 along N
    const int wm = (wid & 3) * 32;
    const int wn = (wid >> 2) * 64;

    float acc[2][8][4];
    #pragma unroll
    for (int a = 0; a < 2; a++)
        #pragma unroll
        for (int b = 0; b < 8; b++)
            #pragma unroll
            for (int c = 0; c < 4; c++) acc[a][b][c] = 0.f;

    const int lr = tid >> 2, lch = tid & 3;   // loader: row, 16B-chunk
    auto load_chunk = [&](int p, int k0) {
        uint32_t buf = sb + p * STG;
        #pragma unroll
        for (int pl = 0; pl < 2; pl++) {
            const __nv_bfloat16* g = gA[pl] + k0;
            #pragma unroll
            for (int it = 0; it < 2; it++) {
                int r = lr + it * 64;
                cp16(buf + pl * A_PL + r * ROWB + lch * 16, g + (long long)r * Ktot + lch * 8);
            }
        }
        #pragma unroll
        for (int pl = 0; pl < 2; pl++) {
            const __nv_bfloat16* g = gB[pl] + k0;
            #pragma unroll
            for (int it = 0; it < 2; it++) {
                int r = lr + it * 64;
                cp16(buf + 2 * A_PL + pl * B_PL + r * ROWB + lch * 16,
                     g + (long long)r * Ktot + lch * 8);
            }
        }
        cp_commit();
    };

    const int nc = Ktot >> 5;
    load_chunk(0, 0);

    const int a_row = wm + (lid & 15);
    const int a_kb  = (lid >> 4) * 16;
    const int b_row = wn + (lid & 7) + ((lid >> 4) & 1) * 8;
    const int b_kb  = ((lid >> 3) & 1) * 16;

    for (int i = 0; i < nc; i++) {
        if (i + 1 < nc) { load_chunk((i + 1) & 1, (i + 1) << 5); cp_wait1(); }
        else            { cp_wait0(); }
        __syncthreads();

        const uint32_t buf = sb + (i & 1) * STG;
        #pragma unroll
        for (int kk = 0; kk < 2; kk++) {
            const uint32_t koff = kk * 32;
            uint32_t Af[2][2][4];
            #pragma unroll
            for (int pl = 0; pl < 2; pl++)
                #pragma unroll
                for (int mb = 0; mb < 2; mb++)
                    ldsm_x4(Af[pl][mb][0], Af[pl][mb][1], Af[pl][mb][2], Af[pl][mb][3],
                            buf + pl * A_PL + (a_row + mb * 16) * ROWB + koff + a_kb);
            #pragma unroll
            for (int nq = 0; nq < 4; nq++) {
                uint32_t BH[4], BL[4];
                const uint32_t bb = buf + 2 * A_PL + (b_row + nq * 16) * ROWB + koff + b_kb;
                ldsm_x4(BH[0], BH[1], BH[2], BH[3], bb);
                ldsm_x4(BL[0], BL[1], BL[2], BL[3], bb + B_PL);
                // pass-outer ordering: 4 independent accumulators between reuses
                #pragma unroll
                for (int mb = 0; mb < 2; mb++)
                    #pragma unroll
                    for (int half = 0; half < 2; half++) {
                        float* c = acc[mb][nq * 2 + half];
                        mma_bf16(c[0], c[1], c[2], c[3],
                                 Af[0][mb][0], Af[0][mb][1], Af[0][mb][2], Af[0][mb][3],
                                 BH[half * 2], BH[half * 2 + 1]);
                    }
                #pragma unroll
                for (int mb = 0; mb < 2; mb++)
                    #pragma unroll
                    for (int half = 0; half < 2; half++) {
                        float* c = acc[mb][nq * 2 + half];
                        mma_bf16(c[0], c[1], c[2], c[3],
                                 Af[0][mb][0], Af[0][mb][1], Af[0][mb][2], Af[0][mb][3],
                                 BL[half * 2], BL[half * 2 + 1]);
                    }
                #pragma unroll
                for (int mb = 0; mb < 2; mb++)
                    #pragma unroll
                    for (int half = 0; half < 2; half++) {
                        float* c = acc[mb][nq * 2 + half];
                        mma_bf16(c[0], c[1], c[2], c[3],
                                 Af[1][mb][0], Af[1][mb][1], Af[1][mb][2], Af[1][mb][3],
                                 BH[half * 2], BH[half * 2 + 1]);
                    }
            }
        }
        __syncthreads();
    }

    // epilogue
    const int er = lid >> 2;
    const int ec = (lid & 3) * 2;
    #pragma unroll
    for (int mb = 0; mb < 2; mb++) {
        #pragma unroll
        for (int nb = 0; nb < 8; nb++) {
            const float* c = acc[mb][nb];
            long long col = bn + wn + nb * 8 + ec;
            float bx = 0.f, by = 0.f;
            if (biasp) { bx = biasp[col]; by = biasp[col + 1]; }
            long long r0 = bm + wm + mb * 16 + er;
            float v0 = c[0] + bx, v1 = c[1] + by;
            float v2 = c[2] + bx, v3 = c[3] + by;
            if (Cf) {
                float* Cb = Cf + bz * sC;
                *reinterpret_cast<float2*>(Cb + r0 * N + col) = make_float2(v0, v1);
                *reinterpret_cast<float2*>(Cb + (r0 + 8) * N + col) = make_float2(v2, v3);
            } else {
                __nv_bfloat16 h0 = __float2bfloat16(v0), h1 = __float2bfloat16(v1);
                __nv_bfloat16 h2 = __float2bfloat16(v2), h3 = __float2bfloat16(v3);
                __nv_bfloat162 hp0 = { h0, h1 }, hp1 = { h2, h3 };
                __nv_bfloat162 lp0 = { __float2bfloat16(v0 - __bfloat162float(h0)),
                                       __float2bfloat16(v1 - __bfloat162float(h1)) };
                __nv_bfloat162 lp1 = { __float2bfloat16(v2 - __bfloat162float(h2)),
                                       __float2bfloat16(v3 - __bfloat162float(h3)) };
                __nv_bfloat16* Hb = Ch + bz * sC;
                __nv_bfloat16* Lb = Cl + bz * sC;
                *reinterpret_cast<__nv_bfloat162*>(Hb + r0 * N + col) = hp0;
                *reinterpret_cast<__nv_bfloat162*>(Hb + (r0 + 8) * N + col) = hp1;
                *reinterpret_cast<__nv_bfloat162*>(Lb + r0 * N + col) = lp0;
                *reinterpret_cast<__nv_bfloat162*>(Lb + (r0 + 8) * N + col) = lp1;
            }
        }
    }
}

// ---------------- prep kernels ----------------
__global__ void split_conv(const float* __restrict__ s, __nv_bfloat16* __restrict__ h,
                           __nv_bfloat16* __restrict__ l, long long n)
{
    long long i = (long long)blockIdx.x * blockDim.x + threadIdx.x;
    if (i < n) {
        float v = s[i];
        __nv_bfloat16 hi = __float2bfloat16(v);
        h[i] = hi;
        l[i] = __float2bfloat16(v - __bfloat162float(hi));
    }
}

// fp32 [R,C] -> bf16 hi/lo [C,R] (for the weight matrices)
__global__ void transpose_split(const float* __restrict__ src,
                                __nv_bfloat16* __restrict__ dh, __nv_bfloat16* __restrict__ dl,
                                int R, int C)
{
    __shared__ float t[32][33];
    int c0 = blockIdx.x * 32, r0 = blockIdx.y * 32;
    int tx = threadIdx.x, ty = threadIdx.y;
    #pragma unroll
    for (int k = 0; k < 32; k += 8)
        t[ty + k][tx] = src[(long long)(r0 + ty + k) * C + c0 + tx];
    __syncthreads();
    #pragma unroll
    for (int k = 0; k < 32; k += 8) {
        float v = t[tx][ty + k];
        __nv_bfloat16 hi = __float2bfloat16(v);
        long long o = (long long)(c0 + ty + k) * R + r0 + tx;
        dh[o] = hi;
        dl[o] = __float2bfloat16(v - __bfloat162float(hi));
    }
}

// bf16 pair [R,C] -> [C,R], batched via z. 64x64 tiles, 256 threads.
__global__ void transpose_pair(const __nv_bfloat16* __restrict__ sh,
                               const __nv_bfloat16* __restrict__ sl,
                               __nv_bfloat16* __restrict__ dh, __nv_bfloat16* __restrict__ dl,
                               int R, int C, long long sIn, long long sOut)
{
    __shared__ __nv_bfloat16 th[64][65], tl[64][65];
    int b = blockIdx.z;
    sh += (long long)b * sIn; sl += (long long)b * sIn;
    dh += (long long)b * sOut; dl += (long long)b * sOut;
    int c0 = blockIdx.x * 64, r0 = blockIdx.y * 64;
    int tid = threadIdx.x;
    #pragma unroll
    for (int it = 0; it < 8; it++) {
        int id = tid + it * 256;
        int row = id >> 5, cp = (id & 31) * 2;
        long long src = (long long)(r0 + row) * C + c0 + cp;
        __nv_bfloat162 vh = *reinterpret_cast<const __nv_bfloat162*>(sh + src);
        __nv_bfloat162 vl = *reinterpret_cast<const __nv_bfloat162*>(sl + src);
        th[row][cp] = vh.x; th[row][cp + 1] = vh.y;
        tl[row][cp] = vl.x; tl[row][cp + 1] = vl.y;
    }
    __syncthreads();
    #pragma unroll
    for (int it = 0; it < 8; it++) {
        int id = tid + it * 256;
        int cc = id >> 5, rp = (id & 31) * 2;
        long long dst = (long long)(c0 + cc) * R + r0 + rp;
        __nv_bfloat162 vh = { th[rp][cc], th[rp + 1][cc] };
        __nv_bfloat162 vl = { tl[rp][cc], tl[rp + 1][cc] };
        *reinterpret_cast<__nv_bfloat162*>(dh + dst) = vh;
        *reinterpret_cast<__nv_bfloat162*>(dl + dst) = vl;
    }
}

__global__ void zero_s(float* p) { p[blockIdx.x * 256 + threadIdx.x] = 0.f; }

__global__ void reduce_s2(const float* __restrict__ G, float* __restrict__ s)
{
    int b = blockIdx.z;
    int n = blockIdx.x * 256 + threadIdx.x;
    int j0 = blockIdx.y * 128;
    const float* Gb = G + ((long long)b << 20);
    float acc = 0.f;
    #pragma unroll 4
    for (int j = j0; j < j0 + 128; j++)
        acc += Gb[((long long)j << 10) + ((n - j) & (Dd - 1))];
    atomicAdd(&s[b * Dd + n], acc);
}

__global__ void build_M_split(const float* __restrict__ s,
                              __nv_bfloat16* __restrict__ h, __nv_bfloat16* __restrict__ l)
{
    int b = blockIdx.z, k = blockIdx.y;
    int n = blockIdx.x * 256 + threadIdx.x;
    float v = s[b * Dd + ((k + n) & (Dd - 1))];
    __nv_bfloat16 hi = __float2bfloat16(v);
    long long o = ((long long)b << 20) + ((long long)k << 10) + n;
    h[o] = hi;
    l[o] = __float2bfloat16(v - __bfloat162float(hi));
}

__global__ void compute_r(const float* __restrict__ s, const float* __restrict__ bq,
                          float* __restrict__ r)
{
    int b = blockIdx.y;
    int n = blockIdx.x * 256 + threadIdx.x;
    float acc = 0.f;
    for (int m = 0; m < Dd; m++)
        acc += bq[m] * s[b * Dd + ((m + n) & (Dd - 1))];
    r[b * Dd + n] = acc;
}

// ---------------- launcher ----------------
extern "C" void kernel_launch(void* const* d_in, const int* in_sizes, int n_in,
                              void* d_out, int out_size)
{
    const float* x  = (const float*)d_in[0];
    const float* Wq = (const float*)d_in[1];
    const float* bq = (const float*)d_in[2];
    const float* Wk = (const float*)d_in[3];
    const float* bk = (const float*)d_in[4];
    const float* Wv = (const float*)d_in[5];
    const float* bv = (const float*)d_in[6];
    float* out = (float*)d_out;

    __nv_bfloat16 *xh, *xl, *WkTh, *WkTl, *WvTh, *WvTl, *Wqh, *Wql;
    __nv_bfloat16 *Kh, *Kl, *Vh, *Vl, *KTh, *KTl, *VTh, *VTl, *Mh, *Ml, *W2Th, *W2Tl;
    float *G, *s, *r;
    cudaGetSymbolAddress((void**)&xh, g_xh);     cudaGetSymbolAddress((void**)&xl, g_xl);
    cudaGetSymbolAddress((void**)&WkTh, g_WkTh); cudaGetSymbolAddress((void**)&WkTl, g_WkTl);
    cudaGetSymbolAddress((void**)&WvTh, g_WvTh); cudaGetSymbolAddress((void**)&WvTl, g_WvTl);
    cudaGetSymbolAddress((void**)&Wqh, g_Wqh);   cudaGetSymbolAddress((void**)&Wql, g_Wql);
    cudaGetSymbolAddress((void**)&Kh, g_Kh);     cudaGetSymbolAddress((void**)&Kl, g_Kl);
    cudaGetSymbolAddress((void**)&Vh, g_Vh);     cudaGetSymbolAddress((void**)&Vl, g_Vl);
    cudaGetSymbolAddress((void**)&KTh, g_KTh);   cudaGetSymbolAddress((void**)&KTl, g_KTl);
    cudaGetSymbolAddress((void**)&VTh, g_VTh);   cudaGetSymbolAddress((void**)&VTl, g_VTl);
    cudaGetSymbolAddress((void**)&G, g_G);       cudaGetSymbolAddress((void**)&s, g_s);
    cudaGetSymbolAddress((void**)&r, g_r);
    cudaGetSymbolAddress((void**)&Mh, g_Mh);     cudaGetSymbolAddress((void**)&Ml, g_Ml);
    cudaGetSymbolAddress((void**)&W2Th, g_W2Th); cudaGetSymbolAddress((void**)&W2Tl, g_W2Tl);

    cudaFuncSetAttribute(gemm_hmma, cudaFuncAttributeMaxDynamicSharedMemorySize, GEMM_DSMEM);

    const long long nBS = (long long)BS * Dd;       // 16M
    const long long dd  = (long long)Dd * Dd;       // 1M
    const long long sd  = (long long)Sq * Dd;       // 4M

    // 0) input conversion
    split_conv<<<(unsigned)((nBS + 255) / 256), 256>>>(x, xh, xl, nBS);
    transpose_split<<<dim3(Dd / 32, Dd / 32), dim3(32, 8)>>>(Wk, WkTh, WkTl, Dd, Dd);
    transpose_split<<<dim3(Dd / 32, Dd / 32), dim3(32, 8)>>>(Wv, WvTh, WvTl, Dd, Dd);
    split_conv<<<(unsigned)((dd + 255) / 256), 256>>>(Wq, Wqh, Wql, dd);

    // 1) K = x@Wk + bk ; V = x@Wv + bv  -> bf16 hi/lo [BS, D]
    gemm_hmma<<<dim3(Dd / 128, BS / 128, 1), 256, GEMM_DSMEM>>>(
        xh, xl, WkTh, WkTl, bk, nullptr, Kh, Kl, Dd, Dd, 0, 0, 0, 0);
    gemm_hmma<<<dim3(Dd / 128, BS / 128, 1), 256, GEMM_DSMEM>>>(
        xh, xl, WvTh, WvTl, bv, nullptr, Vh, Vl, Dd, Dd, 0, 0, 0, 0);

    // 2) per-batch transpose: [Sq, D] -> [D, Sq]
    transpose_pair<<<dim3(Dd / 64, Sq / 64, Bsz), 256>>>(Kh, Kl, KTh, KTl, Sq, Dd, sd, sd);
    transpose_pair<<<dim3(Dd / 64, Sq / 64, Bsz), 256>>>(Vh, Vl, VTh, VTl, Sq, Dd, sd, sd);

    // 3) G_b = K_b^T @ V_b  (M=N=1024, K=4096, batched)
    gemm_hmma<<<dim3(Dd / 128, Dd / 128, Bsz), 256, GEMM_DSMEM>>>(
        KTh, KTl, VTh, VTl, nullptr, G, nullptr, nullptr, Dd, Sq, sd, sd, 0, dd);

    // 4) s_b = circular anti-diagonal sum of G_b
    zero_s<<<Bsz * Dd / 256, 256>>>(s);
    reduce_s2<<<dim3(Dd / 256, 8, Bsz), 256>>>(G, s);

    // 5) M_b (bf16 hi/lo), r_b = bq @ M_b
    build_M_split<<<dim3(Dd / 256, Dd, Bsz), 256>>>(s, Mh, Ml);
    compute_r<<<dim3(Dd / 256, Bsz), 256>>>(s, bq, r);

    // 6) W2T_b = M_b @ Wq^T -> bf16 hi/lo directly (M is symmetric; see R2 derivation)
    gemm_hmma<<<dim3(Dd / 128, Dd / 128, Bsz), 256, GEMM_DSMEM>>>(
        Mh, Ml, Wqh, Wql, nullptr, nullptr, W2Th, W2Tl, Dd, Dd, dd, 0, 0, dd);

    // 7) out_b = x_b @ W2_b + r_b
    gemm_hmma<<<dim3(Dd / 128, Sq / 128, Bsz), 256, GEMM_DSMEM>>>(
        xh, xl, W2Th, W2Tl, r, out, nullptr, nullptr, Dd, Dd, sd, dd, Dd, sd);
}